// round 17
// baseline (speedup 1.0000x reference)
#include <cuda_runtime.h>
#include <cuda_fp16.h>
#include <math.h>
#include <stdint.h>

// Problem constants
#define NN 9216      // H*W = 96*96
#define CC 64        // channels
#define C8 8         // C/8
#define BB 2         // batch
#define KT 64        // key tile
#define NT (NN / KT) // 144 tiles total
#define NTH (NT / 2) // 72 tiles per key-half
#define QT 128       // query tile per CTA
#define NQT (NN / QT)// 72 query tiles
#define NTL 576      // NN/16 f-tiles per batch
#define SHIFT 9.70406053f   // 14*ln2: P scaled by 2^14 (cancels in O/l)
#define LOG2E 1.44269504f

// -------- scratch (static device globals: no runtime allocation) ----------
__device__ float    d_invsig[3];                // 1/sigma for Wq, Wk, Wv
__device__ uint32_t d_f16[BB * NTL * 32 * 4];   // f~ hi/lo fp16 A-fragments
__device__ float    d_g[BB * NN * C8];          // raw queries g~ = Wk x
__device__ uint32_t d_h16[BB * NN * 32];        // raw h~ fp16 pairs [n][c]
__device__ float    d_fmax2[72];                // per-prep-block max ||f~||^2
__device__ float    d_pO[BB * NQT * 2 * CC * QT];  // partial O~ [b][qt][z][c][q]
__device__ float    d_pl[BB * NQT * 2 * QT];       // partial l

// ---------------- helpers -----------------
__device__ __forceinline__ uint32_t pack_f16(float hi, float lo) {
    uint32_t r;
    asm("cvt.rn.f16x2.f32 %0, %1, %2;" : "=r"(r) : "f"(hi), "f"(lo));
    return r;
}
__device__ __forceinline__ float ex2(float x) {
    float y;
    asm("ex2.approx.f32 %0, %1;" : "=f"(y) : "f"(x));
    return y;
}
__device__ __forceinline__ uint32_t movm(uint32_t s) {
    uint32_t d;
    asm("movmatrix.sync.aligned.m8n8.trans.b16 %0, %1;" : "=r"(d) : "r"(s));
    return d;
}
__device__ __forceinline__ void ldsm4t(uint32_t& a0, uint32_t& a1,
                                       uint32_t& a2, uint32_t& a3, uint32_t addr) {
    asm volatile("ldmatrix.sync.aligned.m8n8.x4.trans.shared.b16 {%0,%1,%2,%3}, [%4];"
                 : "=r"(a0), "=r"(a1), "=r"(a2), "=r"(a3) : "r"(addr));
}
__device__ __forceinline__ void mma16h(float* d,
        uint32_t a0, uint32_t a1, uint32_t a2, uint32_t a3,
        uint32_t b0, uint32_t b1) {
    asm volatile(
        "mma.sync.aligned.m16n8k16.row.col.f32.f16.f16.f32 "
        "{%0,%1,%2,%3},{%4,%5,%6,%7},{%8,%9},{%0,%1,%2,%3};"
        : "+f"(d[0]), "+f"(d[1]), "+f"(d[2]), "+f"(d[3])
        : "r"(a0), "r"(a1), "r"(a2), "r"(a3), "r"(b0), "r"(b1));
}
__device__ __forceinline__ uint32_t smem_u32(const void* p) {
    uint32_t a;
    asm("{ .reg .u64 t; cvta.to.shared.u64 t, %1; cvt.u32.u64 %0, t; }"
        : "=r"(a) : "l"(p));
    return a;
}
__device__ __forceinline__ void cpasync16(uint32_t dst, const void* src) {
    asm volatile("cp.async.ca.shared.global [%0], [%1], 16;"
                 :: "r"(dst), "l"(src));
}
#define CP_COMMIT() asm volatile("cp.async.commit_group;" ::: "memory")

// ===========================================================================
// K1 (merged, 512 threads): blocks 0-2 spectral norm; blocks 3-74 raw
// projections. Projection blocks: 256 columns x 2 channel-halves:
//   lanes 0-255:   fa[8] + ha[0..31]   (40 outputs)
//   lanes 256-511: ga[8] + ha[32..63]  (40 outputs)
// 16 warps/SM for latency hiding.
// ===========================================================================
#define SQ_ITERS 4
#define PW_ITERS 16

__global__ void __launch_bounds__(512) prep_kernel(
        const float* __restrict__ x,
        const float* __restrict__ Wq,
        const float* __restrict__ Wk,
        const float* __restrict__ Wv) {
    __shared__ float shb[8448];
    __shared__ float part[16];
    __shared__ float scal;
    int t = threadIdx.x;

    if (blockIdx.x < 3) {
        int mat = blockIdx.x;
        const float* W = (mat == 0) ? Wq : (mat == 1) ? Wk : Wv;
        int dim = (mat == 2) ? 64 : 8;
        float* Ga = shb;                 // 64*65
        float* Gb = shb + 4160;          // 64*65 (also W staging)
        float* vv = shb + 8320;          // 64

        for (int i = t; i < dim * 64; i += 512)
            Gb[(i >> 6) * 65 + (i & 63)] = W[i];
        __syncthreads();

        if (dim == 64) {
            int r = t >> 3, c0 = (t & 7) << 3;
            float rr[64];
#pragma unroll
            for (int j = 0; j < 64; j++) rr[j] = Gb[r * 65 + j];
            float acc[8];
#pragma unroll
            for (int cc = 0; cc < 8; cc++) acc[cc] = 0.f;
            for (int j = 0; j < 64; j++)
#pragma unroll
                for (int cc = 0; cc < 8; cc++)
                    acc[cc] += rr[j] * Gb[(c0 + cc) * 65 + j];
#pragma unroll
            for (int cc = 0; cc < 8; cc++) Ga[r * 65 + c0 + cc] = acc[cc];
        } else if (t < 64) {
            int r = t >> 3, c = t & 7;
            float s = 0.f;
            for (int j = 0; j < 64; j++) s += Gb[r * 65 + j] * Gb[c * 65 + j];
            Ga[r * 65 + c] = s;
        }
        __syncthreads();

        float logl = 0.f, pw = 1.f;
        float* src = Ga;
        float* dst = Gb;
        for (int it = 0; it < SQ_ITERS; it++) {
            float ss = 0.f;
            for (int e = t; e < dim * dim; e += 512) {
                float v = src[(e / dim) * 65 + (e % dim)];
                ss += v * v;
            }
#pragma unroll
            for (int o = 16; o > 0; o >>= 1)
                ss += __shfl_xor_sync(0xffffffffu, ss, o);
            if ((t & 31) == 0) part[t >> 5] = ss;
            __syncthreads();
            float tot = 0.f;
#pragma unroll
            for (int i = 0; i < 16; i++) tot += part[i];
            float fro = sqrtf(tot);
            float inv2 = 1.f / tot;
            logl += log2f(fro) * pw;
            pw *= 0.5f;

            if (dim == 64) {
                int r = t >> 3, c0 = (t & 7) << 3;
                float rr[64];
#pragma unroll
                for (int j = 0; j < 64; j++) rr[j] = src[r * 65 + j];
                float acc[8];
#pragma unroll
                for (int cc = 0; cc < 8; cc++) acc[cc] = 0.f;
                for (int j = 0; j < 64; j++)
#pragma unroll
                    for (int cc = 0; cc < 8; cc++)
                        acc[cc] += rr[j] * src[j * 65 + c0 + cc];
#pragma unroll
                for (int cc = 0; cc < 8; cc++)
                    dst[r * 65 + c0 + cc] = acc[cc] * inv2;
            } else if (t < 64) {
                int r = t >> 3, c = t & 7;
                float s = 0.f;
#pragma unroll
                for (int j = 0; j < 8; j++) s += src[r * 65 + j] * src[j * 65 + c];
                dst[r * 65 + c] = s * inv2;
            }
            __syncthreads();
            float* tmp = src; src = dst; dst = tmp;
        }

        if (t < 64) vv[t] = 1.f;
        __syncthreads();
        float lam = 1.f;
        for (int it = 0; it < PW_ITERS; it++) {
            float w = 0.f;
            if (t < dim) {
                const float* gr = src + t * 65;
                for (int j = 0; j < dim; j++) w += gr[j] * vv[j];
            }
            float sq = w * w;
#pragma unroll
            for (int o = 16; o > 0; o >>= 1)
                sq += __shfl_xor_sync(0xffffffffu, sq, o);
            if ((t & 31) == 0) part[t >> 5] = sq;
            __syncthreads();
            if (t == 0) scal = sqrtf(part[0] + part[1]);
            __syncthreads();
            lam = scal;
            if (t < dim) vv[t] = w / lam;
            __syncthreads();
        }
        if (t == 0) {
            float l0 = log2f(lam) * pw + logl;
            d_invsig[mat] = exp2f(-0.5f * l0);
        }
    } else {
        float* wq = shb;            // 512
        float* wk = shb + 512;      // 512
        float* wv = shb + 1024;     // 4096

        for (int i = t; i < 512; i += 512) { wq[i] = Wq[i]; wk[i] = Wk[i]; }
        for (int i = t; i < 4096; i += 512) wv[i] = Wv[i];
        __syncthreads();

        int tt = t & 255;
        int half = t >> 8;                          // 0 or 1
        int gid = (blockIdx.x - 3) * 256 + tt;      // 0 .. 18431
        int b = gid / NN, n = gid % NN;
        int cb = half * 32;                         // this half's h channels

        float pa[8] = {0.f};                        // fa (half0) / ga (half1)
        float ha[32] = {0.f};
        const float* xp = x + (size_t)b * CC * NN + n;
        const float* wp = half ? wk : wq;
        for (int c = 0; c < 64; c++) {
            float xc = xp[(size_t)c * NN];
#pragma unroll
            for (int o = 0; o < 8; o++)
                pa[o] += wp[o * 64 + c] * xc;
#pragma unroll
            for (int o = 0; o < 32; o++)
                ha[o] += wv[(cb + o) * 64 + c] * xc;
        }

        if (half == 0) {
            // f: fp16 hi/lo pairs in m16n8k16 A-fragment layout.
            int tl = n >> 4, r = n & 15;
            uint32_t* fb = d_f16 + ((size_t)(b * NTL + tl) * 32
                                    + 4 * (r & 7)) * 4 + ((r >> 3) & 1);
#pragma unroll
            for (int c = 0; c < 4; c++) {
                __half h0 = __float2half_rn(pa[2 * c]);
                __half h1 = __float2half_rn(pa[2 * c + 1]);
                float l0 = pa[2 * c]     - __half2float(h0);
                float l1 = pa[2 * c + 1] - __half2float(h1);
                uint32_t hi = ((uint32_t)__half_as_ushort(h1) << 16)
                            | __half_as_ushort(h0);
                fb[c * 4]     = hi;
                fb[c * 4 + 2] = pack_f16(l1, l0);
            }
        } else {
            // g raw
            size_t b8 = ((size_t)b * NN + n) * 8;
#pragma unroll
            for (int o = 0; o < 8; o++) d_g[b8 + o] = pa[o];
        }

        // h: raw fp16 pairs [n][c], this half's 4 uint4s
        {
            uint32_t hw[16];
#pragma unroll
            for (int i = 0; i < 16; i++)
                hw[i] = pack_f16(ha[2 * i + 1], ha[2 * i]);
            uint4* hp = (uint4*)(d_h16 + ((size_t)b * NN + n) * 32) + half * 4;
#pragma unroll
            for (int j = 0; j < 4; j++)
                hp[j] = make_uint4(hw[4 * j], hw[4 * j + 1],
                                   hw[4 * j + 2], hw[4 * j + 3]);
        }

        // block max of ||f~||^2 (half 0 holds f)
        float n2 = 0.f;
        if (half == 0) {
#pragma unroll
            for (int o = 0; o < 8; o++) n2 += pa[o] * pa[o];
        }
#pragma unroll
        for (int o = 16; o > 0; o >>= 1)
            n2 = fmaxf(n2, __shfl_xor_sync(0xffffffffu, n2, o));
        if ((t & 31) == 0) part[t >> 5] = n2;
        __syncthreads();
        if (t == 0) {
            float m = part[0];
#pragma unroll
            for (int i = 1; i < 16; i++) m = fmaxf(m, part[i]);
            d_fmax2[blockIdx.x - 3] = m;
        }
    }
}

// ===========================================================================
// K2: flash attention, tensor-core, KT=64, QT=128, SPLIT-K over 2 CTAs.
//   (unchanged from R15)
// ===========================================================================
__global__ void __launch_bounds__(256, 2) attn_kernel(
        const float* __restrict__ bk,
        float* __restrict__ pO_out,
        float* __restrict__ pl_out) {
    __shared__ __align__(16) uint32_t hbuf[3][2048];   // 3 x 8KB fp16 H tiles
    __shared__ float g_sh[QT * 9];
    __shared__ float red8[8];

    int t    = threadIdx.x;
    int wid  = t >> 5;
    int lane = t & 31;
    int qt   = blockIdx.x;
    int b    = blockIdx.y;
    int z    = blockIdx.z;

    float iq = d_invsig[0], ik = d_invsig[1];

    // stage g tile (scaled + bias): 128 queries
    const float* gp = d_g + ((size_t)b * NN + (size_t)qt * QT) * 8;
    for (int i = t; i < QT * 8; i += 256)
        g_sh[(i >> 3) * 9 + (i & 7)] = ik * gp[i] + __ldg(bk + (i & 7));

    // Fmax^2 reduction (72 values)
    {
        float fm = (t < 72) ? d_fmax2[t] : 0.f;
#pragma unroll
        for (int o = 16; o > 0; o >>= 1)
            fm = fmaxf(fm, __shfl_xor_sync(0xffffffffu, fm, o));
        if (lane == 0) red8[wid] = fm;
    }

    // H staging role + prologue cp.async for this half's tiles 0,1
    int srow = t >> 3, sj = t & 7;
    const char* hsrc = (const char*)d_h16
                     + ((size_t)(b * NN + z * NTH * KT + srow)) * 128 + sj * 16;
    uint32_t hb0  = smem_u32(&hbuf[0][0]);
    uint32_t sdst = hb0 + srow * 128 + ((sj ^ (srow & 7)) << 4);
    cpasync16(sdst, hsrc);
    cpasync16(sdst + 4096, hsrc + 4096);
    CP_COMMIT();
    cpasync16(sdst + 8192, hsrc + 8192);
    cpasync16(sdst + 8192 + 4096, hsrc + 8192 + 4096);
    CP_COMMIT();

    __syncthreads();
    float Fmax;
    {
        float fm = red8[0];
#pragma unroll
        for (int i = 1; i < 8; i++) fm = fmaxf(fm, red8[i]);
        Fmax = sqrtf(fm);
    }

    // G B-fragments (fp16 hi/lo) for 2 query groups
    uint32_t bgh[2], bgl[2];
#pragma unroll
    for (int qg = 0; qg < 2; qg++) {
        int qn = 16 * wid + 8 * qg + (lane >> 2);
        int d0 = 2 * (lane & 3);
        float g0 = g_sh[qn * 9 + d0];
        float g1 = g_sh[qn * 9 + d0 + 1];
        __half h0 = __float2half_rn(g0);
        __half h1 = __float2half_rn(g1);
        bgh[qg] = ((uint32_t)__half_as_ushort(h1) << 16) | __half_as_ushort(h0);
        bgl[qg] = pack_f16(g1 - __half2float(h1), g0 - __half2float(h0));
    }

    // exp2 constants (identical for both key halves)
    float iq2 = iq * LOG2E;
    float cq2[2][2];
#pragma unroll
    for (int qg = 0; qg < 2; qg++) {
        int qa = 16 * wid + 8 * qg + 2 * (lane & 3);
#pragma unroll
        for (int u = 0; u < 2; u++) {
            float n2 = 0.f;
#pragma unroll
            for (int d = 0; d < 8; d++) {
                float v = g_sh[(qa + u) * 9 + d];
                n2 += v * v;
            }
            cq2[qg][u] = (SHIFT - iq * Fmax * sqrtf(n2)) * LOG2E;
        }
    }

    // ldsm.trans A-frag address pieces
    int lm = lane & 7, g1b = (lane >> 3) & 1, g2b = lane >> 4;
    uint32_t rowbase = hb0 + (g2b * 8 + lm) * 128;
    uint32_t colX[4];
#pragma unroll
    for (int ct = 0; ct < 4; ct++)
        colX[ct] = (uint32_t)(((2 * ct + g1b) ^ lm) << 4);

    float acc[4][2][4];
#pragma unroll
    for (int i = 0; i < 4; i++)
#pragma unroll
        for (int qg = 0; qg < 2; qg++)
#pragma unroll
            for (int j = 0; j < 4; j++) acc[i][qg][j] = 0.f;
    float ls[2][2] = {{0.f, 0.f}, {0.f, 0.f}};

    const uint4* fbase = (const uint4*)d_f16
                       + ((size_t)b * NTL + (size_t)z * NTH * 4) * 32 + lane;

    for (int kt = 0; kt < NTH; kt++) {
        int cur = kt % 3;

        if (kt < NTH - 1)
            asm volatile("cp.async.wait_group 1;" ::: "memory");
        else
            asm volatile("cp.async.wait_group 0;" ::: "memory");
        __syncthreads();

        if (kt + 2 < NTH) {
            uint32_t nb = ((kt + 2) % 3) * 8192;
            const char* hs = hsrc + (size_t)(kt + 2) * 8192;
            cpasync16(sdst + nb, hs);
            cpasync16(sdst + nb + 4096, hs + 4096);
            CP_COMMIT();
        }

        // f fragments for this tile (occupancy hides L2 latency)
        uint4 fA[4];
#pragma unroll
        for (int mt = 0; mt < 4; mt++)
            fA[mt] = __ldg(fbase + (size_t)(kt * 4 + mt) * 32);

        // ---- scores: fp16 mma, 2 q-groups ----
        uint32_t Bh[4][2][2];
#pragma unroll
        for (int mt = 0; mt < 4; mt++) {
#pragma unroll
            for (int qg = 0; qg < 2; qg++) {
                float D[4] = {0.f, 0.f, 0.f, 0.f};
                mma16h(D, fA[mt].x, fA[mt].y, fA[mt].z, fA[mt].w,
                       bgh[qg], bgh[qg]);
                mma16h(D, fA[mt].x, fA[mt].y, fA[mt].z, fA[mt].w,
                       bgl[qg], bgl[qg]);

                float p0 = ex2(fmaf(iq2, D[0], cq2[qg][0]));
                float p1 = ex2(fmaf(iq2, D[1], cq2[qg][1]));
                float p2 = ex2(fmaf(iq2, D[2], cq2[qg][0]));
                float p3 = ex2(fmaf(iq2, D[3], cq2[qg][1]));
                ls[qg][0] += p0 + p2;
                ls[qg][1] += p1 + p3;

                Bh[mt][qg][0] = movm(pack_f16(p1, p0));
                Bh[mt][qg][1] = movm(pack_f16(p3, p2));
            }
        }

        // ---- PV: O += H~ * P (each ldsm feeds 2 mma) ----
        uint32_t bufo = cur * 8192;
#pragma unroll
        for (int ct = 0; ct < 4; ct++) {
#pragma unroll
            for (int ks = 0; ks < 4; ks++) {
                uint32_t a0, a1, a2, a3;
                ldsm4t(a0, a1, a2, a3,
                       rowbase + bufo + ks * 2048 + colX[ct]);
                mma16h(acc[ct][0], a0, a1, a2, a3, Bh[ks][0][0], Bh[ks][0][1]);
                mma16h(acc[ct][1], a0, a1, a2, a3, Bh[ks][1][0], Bh[ks][1][1]);
            }
        }
    }

    // ---- partial denominators (sums, no reciprocal) ----
#pragma unroll
    for (int qg = 0; qg < 2; qg++) {
#pragma unroll
        for (int u = 0; u < 2; u++) {
            float v = ls[qg][u];
            v += __shfl_xor_sync(0xffffffffu, v, 4);
            v += __shfl_xor_sync(0xffffffffu, v, 8);
            v += __shfl_xor_sync(0xffffffffu, v, 16);
            ls[qg][u] = v;
        }
    }

    // ---- write partials ----
    size_t pb = (((size_t)b * NQT + qt) * 2 + z);
    float* pO = pO_out + pb * (CC * QT);
    if (lane < 4) {
#pragma unroll
        for (int qg = 0; qg < 2; qg++) {
            int q0 = 16 * wid + 8 * qg + 2 * lane;
            pl_out[pb * QT + q0]     = ls[qg][0];
            pl_out[pb * QT + q0 + 1] = ls[qg][1];
        }
    }
#pragma unroll
    for (int ct = 0; ct < 4; ct++) {
        int c0 = ct * 16 + (lane >> 2);
#pragma unroll
        for (int qg = 0; qg < 2; qg++) {
            int q0 = 16 * wid + 8 * qg + 2 * (lane & 3);
            float2 v0 = make_float2(acc[ct][qg][0], acc[ct][qg][1]);
            float2 v1 = make_float2(acc[ct][qg][2], acc[ct][qg][3]);
            *(float2*)(pO + c0 * QT + q0) = v0;
            *(float2*)(pO + (c0 + 8) * QT + q0) = v1;
        }
    }
}

// ===========================================================================
// K3: combine the 2 key-half partials + epilogue. (unchanged from R15)
// ===========================================================================
__global__ void __launch_bounds__(256) combine_kernel(
        const float* __restrict__ x,
        const float* __restrict__ bv,
        const float* __restrict__ gamma,
        float* __restrict__ out) {
    __shared__ float linv[QT];
    int t  = threadIdx.x;
    int qt = blockIdx.x;
    int b  = blockIdx.y;

    size_t pb = ((size_t)b * NQT + qt) * 2;
    if (t < QT) {
        float l = d_pl[pb * QT + t] + d_pl[(pb + 1) * QT + t];
        linv[t] = 1.f / l;
    }
    __syncthreads();

    float gam = gamma[0];
    float giv = gam * d_invsig[2];
    const float* p0 = d_pO + pb * (CC * QT);
    const float* p1 = p0 + CC * QT;

    int c  = t >> 2;
    int qs = (t & 3) * 32;
    float gb = gam * __ldg(bv + c);
    size_t xb = ((size_t)b * CC + c) * NN + (size_t)qt * QT;

#pragma unroll
    for (int j = 0; j < 8; j++) {
        int q = qs + 4 * j;
        float4 a  = *(const float4*)(p0 + c * QT + q);
        float4 bb = *(const float4*)(p1 + c * QT + q);
        float4 xin = *(const float4*)(x + xb + q);
        float4 r;
        r.x = giv * (a.x + bb.x) * linv[q]     + gb + xin.x;
        r.y = giv * (a.y + bb.y) * linv[q + 1] + gb + xin.y;
        r.z = giv * (a.z + bb.z) * linv[q + 2] + gb + xin.z;
        r.w = giv * (a.w + bb.w) * linv[q + 3] + gb + xin.w;
        *(float4*)(out + xb + q) = r;
    }
}

// ===========================================================================
extern "C" void kernel_launch(void* const* d_in, const int* in_sizes, int n_in,
                              void* d_out, int out_size) {
    const float* x     = (const float*)d_in[0];
    const float* Wq    = (const float*)d_in[1];
    const float* Wk    = (const float*)d_in[3];
    const float* bk    = (const float*)d_in[4];
    const float* Wv    = (const float*)d_in[5];
    const float* bv    = (const float*)d_in[6];
    const float* gamma = (const float*)d_in[7];
    float* out = (float*)d_out;

    float* pO;
    float* pl;
    cudaGetSymbolAddress((void**)&pO, d_pO);
    cudaGetSymbolAddress((void**)&pl, d_pl);

    prep_kernel<<<3 + (BB * NN) / 256, 512>>>(x, Wq, Wk, Wv);
    attn_kernel<<<dim3(NQT, BB, 2), 256>>>(bk, pO, pl);
    combine_kernel<<<dim3(NQT, BB), 256>>>(x, bv, gamma, out);
}